// round 1
// baseline (speedup 1.0000x reference)
#include <cuda_runtime.h>
#include <stdint.h>

// Problem constants (from reference)
#define BZ   32
#define SEQ  2048
#define D    768
#define P    16
#define PLACEHOLDER_ID 1
#define ROWS (BZ * SEQ)          // 65536
#define D4   (D / 4)             // 192 float4 per row

// Scratch: per-position source code.
//   code >= 0            -> emb_table row index (token id)
//   code <  0 (bit31 set)-> prompt row index = code & 15
__device__ int g_codes[ROWS];

// ---------------------------------------------------------------------------
// Kernel 1: per-batch-row inclusive scan of placeholder mask -> source codes.
// 32 blocks (one per batch row), 256 threads, 8 contiguous ids per thread.
// ---------------------------------------------------------------------------
__global__ void scan_codes_kernel(const int* __restrict__ input_ids) {
    const int row = blockIdx.x;                 // 0..31
    const int* rid = input_ids + row * SEQ;
    int*       rc  = g_codes   + row * SEQ;
    const int t = threadIdx.x;                  // 0..255
    const int base = t * 8;

    int ids[8];
    int cnt = 0;
#pragma unroll
    for (int i = 0; i < 8; i++) {
        ids[i] = rid[base + i];
        cnt += (ids[i] == PLACEHOLDER_ID);
    }

    __shared__ int s[256];
    s[t] = cnt;
    __syncthreads();
    // Hillis-Steele inclusive scan over 256 per-thread counts
#pragma unroll
    for (int off = 1; off < 256; off <<= 1) {
        int v = (t >= off) ? s[t - off] : 0;
        __syncthreads();
        s[t] += v;
        __syncthreads();
    }
    int rank = s[t] - cnt;                      // exclusive prefix for this chunk

#pragma unroll
    for (int i = 0; i < 8; i++) {
        int id = ids[i];
        int code;
        if (id == PLACEHOLDER_ID) {
            int r = rank < (P - 1) ? rank : (P - 1);   // clip (matches reference)
            code = (int)(0x80000000u | (unsigned)r);
            rank++;
        } else {
            code = id;
        }
        rc[base + i] = code;
    }
}

// ---------------------------------------------------------------------------
// Kernel 2: row copy. One block per output row (65536 blocks), 192 threads,
// each thread moves one float4 (16 B). Stores are fully coalesced; loads are
// gathers from emb_table (mostly L2-resident: table ~94 MB < 126 MB L2).
// ---------------------------------------------------------------------------
__global__ __launch_bounds__(D4)
void gather_rows_kernel(const float4* __restrict__ emb,
                        const float4* __restrict__ prompt,
                        float4* __restrict__ out) {
    const int row  = blockIdx.x;
    const int code = g_codes[row];              // broadcast within block (L1)

    const float4* src;
    if (code < 0) {
        src = prompt + (size_t)(code & (P - 1)) * D4;
    } else {
        src = emb + (size_t)code * D4;
    }
    out[(size_t)row * D4 + threadIdx.x] = __ldg(src + threadIdx.x);
}

// ---------------------------------------------------------------------------
// Launch. Inputs (metadata order): input_ids int32 [32,2048],
// emb_table f32 [30522,768], prompt f32 [16,768]. Output f32 [32,2048,768].
// ---------------------------------------------------------------------------
extern "C" void kernel_launch(void* const* d_in, const int* in_sizes, int n_in,
                              void* d_out, int out_size) {
    const int*    input_ids = (const int*)d_in[0];
    const float4* emb       = (const float4*)d_in[1];
    const float4* prompt    = (const float4*)d_in[2];
    float4*       out       = (float4*)d_out;

    scan_codes_kernel<<<BZ, 256>>>(input_ids);
    gather_rows_kernel<<<ROWS, D4>>>(emb, prompt, out);
}

// round 2
// speedup vs baseline: 1.2197x; 1.2197x over previous
#include <cuda_runtime.h>
#include <stdint.h>

// Problem constants
#define BZ   32
#define SEQ  2048
#define D    768
#define P    16
#define PLACEHOLDER_ID 1
#define ROWS (BZ * SEQ)          // 65536
#define D4   (D / 4)             // 192 float4 per row
#define TOTAL4 (ROWS * D4)       // 12,582,912 float4

// Scratch: per-position source code.
//   code >= 0             -> emb_table row index (token id)
//   code <  0 (bit31 set) -> prompt row index = code & 15
__device__ int g_codes[ROWS];

// ---------------------------------------------------------------------------
// Kernel 1: per-batch-row inclusive scan of placeholder mask -> source codes.
// ---------------------------------------------------------------------------
__global__ void scan_codes_kernel(const int* __restrict__ input_ids) {
    const int row = blockIdx.x;                 // 0..31
    const int* rid = input_ids + row * SEQ;
    int*       rc  = g_codes   + row * SEQ;
    const int t = threadIdx.x;                  // 0..255
    const int base = t * 8;

    int ids[8];
    int cnt = 0;
#pragma unroll
    for (int i = 0; i < 8; i++) {
        ids[i] = rid[base + i];
        cnt += (ids[i] == PLACEHOLDER_ID);
    }

    __shared__ int s[256];
    s[t] = cnt;
    __syncthreads();
#pragma unroll
    for (int off = 1; off < 256; off <<= 1) {
        int v = (t >= off) ? s[t - off] : 0;
        __syncthreads();
        s[t] += v;
        __syncthreads();
    }
    int rank = s[t] - cnt;                      // exclusive prefix

#pragma unroll
    for (int i = 0; i < 8; i++) {
        int id = ids[i];
        int code;
        if (id == PLACEHOLDER_ID) {
            int r = rank < (P - 1) ? rank : (P - 1);
            code = (int)(0x80000000u | (unsigned)r);
            rank++;
        } else {
            code = id;
        }
        rc[base + i] = code;
    }
}

// ---------------------------------------------------------------------------
// Kernel 2: gather/copy with high MLP.
// Flat index over all TOTAL4 float4s. Each thread handles ITERS=8 float4s
// (strided by TPB within its block's contiguous chunk). All 8 gather loads
// are issued before any store -> MLP ~8 hides L2/DRAM latency.
// Streaming stores (__stcs) keep the emb table resident in L2.
// ---------------------------------------------------------------------------
#define TPB   256
#define ITERS 8
#define BLOCKS (TOTAL4 / (TPB * ITERS))   // 6144, exact

__global__ __launch_bounds__(TPB)
void gather_rows_kernel(const float4* __restrict__ emb,
                        const float4* __restrict__ prompt,
                        float4* __restrict__ out) {
    const int base = blockIdx.x * (TPB * ITERS) + threadIdx.x;

    int idxs[ITERS];
    const float4* srcs[ITERS];

    // Phase 1: compute source addresses (code loads hit L1/L2, broadcast-ish)
#pragma unroll
    for (int i = 0; i < ITERS; i++) {
        int idx = base + i * TPB;
        idxs[i] = idx;
        int row = idx / D4;          // idx < 2^24: compiler uses mul-hi magic
        int col = idx - row * D4;
        int code = __ldg(&g_codes[row]);
        srcs[i] = (code < 0) ? (prompt + (size_t)(code & (P - 1)) * D4 + col)
                             : (emb    + (size_t)code * D4 + col);
    }

    // Phase 2: issue all independent gather loads back-to-back
    float4 v[ITERS];
#pragma unroll
    for (int i = 0; i < ITERS; i++) {
        v[i] = __ldg(srcs[i]);
    }

    // Phase 3: coalesced streaming stores (don't pollute L2 with output)
#pragma unroll
    for (int i = 0; i < ITERS; i++) {
        __stcs(&out[idxs[i]], v[i]);
    }
}

// ---------------------------------------------------------------------------
extern "C" void kernel_launch(void* const* d_in, const int* in_sizes, int n_in,
                              void* d_out, int out_size) {
    const int*    input_ids = (const int*)d_in[0];
    const float4* emb       = (const float4*)d_in[1];
    const float4* prompt    = (const float4*)d_in[2];
    float4*       out       = (float4*)d_out;

    scan_codes_kernel<<<BZ, 256>>>(input_ids);
    gather_rows_kernel<<<BLOCKS, TPB>>>(emb, prompt, out);
}